// round 17
// baseline (speedup 1.0000x reference)
#include <cuda_runtime.h>
#include <cuda_bf16.h>
#include <math.h>
#include <stdint.h>

// Problem shapes (fixed per reference)
#define N_NODES 20000
#define N_EDGES 40000
#define H 64
#define F_ATOM 62
#define F_BOND 6
#define BGRAPH 512
#define HH 4096          // H*H
#define E_PAD 40064      // 313 * 128, padded edge count for 128-row tiles
#define KSEG 2           // K-range split across CTAs (m-chunks per CTA = 64/KSEG)
#define MCH (64 / KSEG)

// ---------------- scratch (device globals; no allocs allowed) ----------------
__device__ __align__(256) float g_h[N_NODES * H];            // node state (fp32)
__device__ __align__(256) float g_msg[N_NODES * H];          // per-step message accumulator
__device__ __align__(256) float g_act[N_NODES * H];          // atom activation
__device__ __align__(256) __nv_bfloat16 g_mlpb[E_PAD * H];   // edge MLP features (bf16)
__device__ __align__(256) __nv_bfloat16 g_Ewb[H * HH];       // Ew cast to bf16 (same layout)
__device__ __align__(256) float g_gsum[BGRAPH * H];          // graph segment sums

// ---------------- math helpers ----------------
__device__ __forceinline__ float selu_f(float x) {
    const float alpha = 1.6732632423543772f;
    const float scale = 1.0507009873554805f;
    return x > 0.f ? scale * x : scale * alpha * expm1f(x);
}

__device__ __forceinline__ void mma_bf16_16816(float c[4], const uint32_t a[4],
                                               const uint32_t b0, const uint32_t b1) {
    asm volatile(
        "mma.sync.aligned.m16n8k16.row.col.f32.bf16.bf16.f32 "
        "{%0,%1,%2,%3}, {%4,%5,%6,%7}, {%8,%9}, {%0,%1,%2,%3};"
        : "+f"(c[0]), "+f"(c[1]), "+f"(c[2]), "+f"(c[3])
        : "r"(a[0]), "r"(a[1]), "r"(a[2]), "r"(a[3]), "r"(b0), "r"(b1));
}

__device__ __forceinline__ void ldsm_x4(uint32_t r[4], uint32_t saddr) {
    asm volatile("ldmatrix.sync.aligned.m8n8.x4.shared.b16 {%0,%1,%2,%3}, [%4];"
                 : "=r"(r[0]), "=r"(r[1]), "=r"(r[2]), "=r"(r[3]) : "r"(saddr));
}

__device__ __forceinline__ uint32_t pack_bf2(float x, float y) {
    __nv_bfloat162 b2 = __float22bfloat162_rn(make_float2(x, y));
    return *(uint32_t*)&b2;
}

#define CP_ASYNC16(dst_u32, src_ptr) \
    asm volatile("cp.async.cg.shared.global [%0], [%1], 16;" \
                 :: "r"(dst_u32), "l"(src_ptr) : "memory")
#define CP_COMMIT() asm volatile("cp.async.commit_group;" ::: "memory")
#define CP_WAIT0() asm volatile("cp.async.wait_group 0;" ::: "memory")

// ---------------- fused prep: pad h, edge MLP, cast Ew, zero msg ----------------
#define PREP_PAD_BLKS 5000                  // N_NODES*H/256
#define PREP_MLP_BLKS (E_PAD / 4)           // 10016
#define PREP_B_BLKS 1024                    // H*HH/256
#define PREP_ZERO_BLKS 5000                 // N_NODES*H/256
#define PREP_GRID (PREP_PAD_BLKS + PREP_MLP_BLKS + PREP_B_BLKS + PREP_ZERO_BLKS)

__global__ void k_prep(const float* __restrict__ nf, const float* __restrict__ ef,
                       const float* __restrict__ Wm, const float* __restrict__ bm,
                       const float* __restrict__ Ew) {
    int b = blockIdx.x;
    int tid = threadIdx.x;
    if (b < PREP_PAD_BLKS) {
        int idx = b * 256 + tid;
        int n = idx >> 6, c = idx & 63;
        g_h[idx] = (c < F_ATOM) ? nf[n * F_ATOM + c] : 0.f;
    } else if (b < PREP_PAD_BLKS + PREP_MLP_BLKS) {
        __shared__ float s_ef[4][F_BOND];
        int eb = b - PREP_PAD_BLKS;
        int sub = tid >> 6, i = tid & 63;
        int e = eb * 4 + sub;
        if (i < F_BOND) s_ef[sub][i] = (e < N_EDGES) ? ef[e * F_BOND + i] : 0.f;
        __syncthreads();
        float v = bm[i];
#pragma unroll
        for (int f = 0; f < F_BOND; f++) v += s_ef[sub][f] * Wm[f * H + i];
        v = fmaxf(v, 0.f);
        if (e >= N_EDGES) v = 0.f;
        g_mlpb[e * H + i] = __float2bfloat16_rn(v);
    } else if (b < PREP_PAD_BLKS + PREP_MLP_BLKS + PREP_B_BLKS) {
        int o = (b - PREP_PAD_BLKS - PREP_MLP_BLKS) * 256 + tid;
        g_Ewb[o] = __float2bfloat16_rn(Ew[o]);
    } else {
        int idx = (b - PREP_PAD_BLKS - PREP_MLP_BLKS - PREP_B_BLKS) * 256 + tid;
        g_msg[idx] = 0.f;
    }
}

// ============================================================================
// Fused message step v4: register A-fragments + cp.async double-buffered B
// + intra-chunk B-fragment register pipeline.
//   msg[e,i] += sum_{m in seg, j} (mlp[e,m]*h[rng[e],j]) * Ew[m, i*64+j]
// Grid (E_PAD/128, KSEG). 8 warps; warp = 16 edge-rows x 64 cols.
// ============================================================================
__global__ void __launch_bounds__(256, 2) k_medge(const int* __restrict__ dom,
                                                  const int* __restrict__ rng) {
    __shared__ __align__(16) __nv_bfloat16 s_mlpT[64 * 128];  // [m][e], 16 KB
    __shared__ __align__(16) uint32_t s_ew[2][64 * 36];       // Ew chunk, double buffer, 18 KB
    __shared__ int s_dom[128];
    int tid = threadIdx.x;
    int e0 = blockIdx.x * 128;
    int m0 = blockIdx.y * MCH;

    // mlp tile transposed into smem ([m][e])
    {
        int e = tid >> 1, half = tid & 1;
        const uint4* src = (const uint4*)(g_mlpb + (size_t)(e0 + e) * H + half * 32);
        uint4 v[4];
        v[0] = src[0]; v[1] = src[1]; v[2] = src[2]; v[3] = src[3];
        const __nv_bfloat16* bv = (const __nv_bfloat16*)v;
#pragma unroll
        for (int k = 0; k < 32; k++)
            s_mlpT[(half * 32 + k) * 128 + e] = bv[k];
    }
    if (tid < 128) {
        int ge = e0 + tid;
        s_dom[tid] = (ge < N_EDGES) ? dom[ge] : 0;
    }

    int lane = tid & 31, wid = tid >> 5;
    int g_ = lane >> 2, tg = lane & 3;
    int wm = wid * 16;

    // gather h into registers: rows {wm+g, wm+g+8}, 16 j-values each
    float h[2][16];
#pragma unroll
    for (int rs = 0; rs < 2; rs++) {
        int r = wm + g_ + rs * 8;
        int ge = e0 + r;
        int rr = (ge < N_EDGES) ? __ldg(&rng[ge]) : 0;
        const float* hrow = g_h + rr * H;
#pragma unroll
        for (int kk = 0; kk < 4; kk++) {
            float2 lo = *(const float2*)(hrow + kk * 16 + 2 * tg);
            float2 hi = *(const float2*)(hrow + kk * 16 + 8 + 2 * tg);
            h[rs][kk * 4 + 0] = lo.x;
            h[rs][kk * 4 + 1] = lo.y;
            h[rs][kk * 4 + 2] = hi.x;
            h[rs][kk * 4 + 3] = hi.y;
        }
    }

    // cp.async destination offsets for this thread (2 x 16B per chunk)
    int i0 = 2 * tid, i1 = 2 * tid + 1;
    uint32_t so[2];
    so[0] = (uint32_t)__cvta_generic_to_shared(&s_ew[0][0]);
    so[1] = (uint32_t)__cvta_generic_to_shared(&s_ew[1][0]);
    uint32_t d0 = ((i0 >> 3) * 36 + (i0 & 7) * 4) * 4;
    uint32_t d1 = ((i1 >> 3) * 36 + (i1 & 7) * 4) * 4;

    // prologue: async-load chunk m0 into buffer 0
    {
        const uint4* src = (const uint4*)(g_Ewb + (size_t)m0 * HH);
        CP_ASYNC16(so[0] + d0, src + i0);
        CP_ASYNC16(so[1 - 1] + d1, src + i1);   // same buffer 0
        CP_COMMIT();
    }

    int lrow = (lane & 7) + ((lane >> 3) & 1) * 8;
    int lcol = (lane >> 4) * 4;

    float c[8][4] = {};
    int p = 0;

    for (int mc = 0; mc < MCH; mc++) {
        int m = m0 + mc;
        CP_WAIT0();
        __syncthreads();   // buffer p data visible; all warps done reading p^1
        // async-load next chunk into p^1 (overlaps compute on p)
        if (mc < MCH - 1) {
            const uint4* src = (const uint4*)(g_Ewb + (size_t)(m + 1) * HH);
            CP_ASYNC16(so[p ^ 1] + d0, src + i0);
            CP_ASYNC16(so[p ^ 1] + d1, src + i1);
            CP_COMMIT();
        }
        // broadcast mlp scalars for this chunk
        float am0 = __bfloat162float(s_mlpT[m * 128 + wm + g_]);
        float am8 = __bfloat162float(s_mlpT[m * 128 + wm + g_ + 8]);
        uint32_t sew_u32 = so[p];

        // B-fragment register pipeline: preload kk=0
        uint32_t bq[2][4][4];
#pragma unroll
        for (int nt = 0; nt < 4; nt++)
            ldsm_x4(bq[0][nt], sew_u32 + ((nt * 16 + lrow) * 36 + lcol) * 4);

#pragma unroll
        for (int kk = 0; kk < 4; kk++) {
            int cur = kk & 1;
            if (kk < 3) {
#pragma unroll
                for (int nt = 0; nt < 4; nt++)
                    ldsm_x4(bq[cur ^ 1][nt],
                            sew_u32 + ((nt * 16 + lrow) * 36 + (kk + 1) * 8 + lcol) * 4);
            }
            uint32_t a[4];
            a[0] = pack_bf2(am0 * h[0][kk * 4 + 0], am0 * h[0][kk * 4 + 1]);
            a[1] = pack_bf2(am8 * h[1][kk * 4 + 0], am8 * h[1][kk * 4 + 1]);
            a[2] = pack_bf2(am0 * h[0][kk * 4 + 2], am0 * h[0][kk * 4 + 3]);
            a[3] = pack_bf2(am8 * h[1][kk * 4 + 2], am8 * h[1][kk * 4 + 3]);
#pragma unroll
            for (int nt = 0; nt < 4; nt++) {
                mma_bf16_16816(c[nt * 2 + 0], a, bq[cur][nt][0], bq[cur][nt][2]);
                mma_bf16_16816(c[nt * 2 + 1], a, bq[cur][nt][1], bq[cur][nt][3]);
            }
        }
        p ^= 1;
    }

    // flush (padded edges: mlp=0 -> c=0, dom=0 safe)
    int dd0 = s_dom[wm + g_];
    int dd1 = s_dom[wm + g_ + 8];
#pragma unroll
    for (int ni = 0; ni < 8; ni++) {
        int col = ni * 8 + tg * 2;
        atomicAdd(&g_msg[dd0 * H + col + 0], c[ni][0]);
        atomicAdd(&g_msg[dd0 * H + col + 1], c[ni][1]);
        atomicAdd(&g_msg[dd1 * H + col + 0], c[ni][2]);
        atomicAdd(&g_msg[dd1 * H + col + 1], c[ni][3]);
    }
}

// h = selu(msg @ Wu + bu + h); resets msg. 32 nodes/block, 8 nodes/thread. (R13-proven.)
__global__ void __launch_bounds__(256) k_update(const float* __restrict__ Wu,
                                                const float* __restrict__ bu) {
    __shared__ __align__(16) float s_m[32][64];
    int tid = threadIdx.x;
    int i = tid & 63, sub = tid >> 6;
    int n0 = blockIdx.x * 32;
    float4* gm = (float4*)(g_msg + n0 * H);
    float4* sm4 = (float4*)s_m;
    const float4 z4 = make_float4(0.f, 0.f, 0.f, 0.f);
#pragma unroll
    for (int it = 0; it < 2; it++) {
        int idx = it * 256 + tid;
        sm4[idx] = gm[idx];
        gm[idx] = z4;
    }
    __syncthreads();
    float b = bu[i];
    float acc[8] = {b, b, b, b, b, b, b, b};
#pragma unroll 4
    for (int kc = 0; kc < 16; kc++) {
        int k = kc * 4;
        float w0 = Wu[(k + 0) * H + i];
        float w1 = Wu[(k + 1) * H + i];
        float w2 = Wu[(k + 2) * H + i];
        float w3 = Wu[(k + 3) * H + i];
#pragma unroll
        for (int u = 0; u < 8; u++) {
            float4 m4 = *(const float4*)&s_m[sub * 8 + u][k];
            acc[u] = fmaf(m4.x, w0, acc[u]);
            acc[u] = fmaf(m4.y, w1, acc[u]);
            acc[u] = fmaf(m4.z, w2, acc[u]);
            acc[u] = fmaf(m4.w, w3, acc[u]);
        }
    }
#pragma unroll
    for (int u = 0; u < 8; u++) {
        int idx = (n0 + sub * 8 + u) * H + i;
        g_h[idx] = selu_f(acc[u] + g_h[idx]);
    }
}

// act = selu((h @ Wae + bae) @ WR + bR); 32 nodes/block, 8/thread; zeroes gsum. (R13-proven.)
__global__ void __launch_bounds__(256) k_embed(const float* __restrict__ Wae,
                                               const float* __restrict__ bae,
                                               const float* __restrict__ WR,
                                               const float* __restrict__ bR) {
    __shared__ __align__(16) float s_h[32][64];
    __shared__ __align__(16) float s_ae[32][64];
    int tid = threadIdx.x;
    if (blockIdx.x < 128) g_gsum[blockIdx.x * 256 + tid] = 0.f;
    int i = tid & 63, sub = tid >> 6;
    int n0 = blockIdx.x * 32;
    const float4* gh = (const float4*)(g_h + n0 * H);
    float4* sh4 = (float4*)s_h;
#pragma unroll
    for (int it = 0; it < 2; it++) {
        int idx = it * 256 + tid;
        sh4[idx] = gh[idx];
    }
    __syncthreads();
    float b1 = bae[i];
    float ae[8] = {b1, b1, b1, b1, b1, b1, b1, b1};
#pragma unroll 4
    for (int kc = 0; kc < 16; kc++) {
        int k = kc * 4;
        float w0 = Wae[(k + 0) * H + i];
        float w1 = Wae[(k + 1) * H + i];
        float w2 = Wae[(k + 2) * H + i];
        float w3 = Wae[(k + 3) * H + i];
#pragma unroll
        for (int u = 0; u < 8; u++) {
            float4 m4 = *(const float4*)&s_h[sub * 8 + u][k];
            ae[u] = fmaf(m4.x, w0, ae[u]);
            ae[u] = fmaf(m4.y, w1, ae[u]);
            ae[u] = fmaf(m4.z, w2, ae[u]);
            ae[u] = fmaf(m4.w, w3, ae[u]);
        }
    }
#pragma unroll
    for (int u = 0; u < 8; u++) s_ae[sub * 8 + u][i] = ae[u];
    __syncthreads();
    float b2 = bR[i];
    float acc[8] = {b2, b2, b2, b2, b2, b2, b2, b2};
#pragma unroll 4
    for (int kc = 0; kc < 16; kc++) {
        int k = kc * 4;
        float w0 = WR[(k + 0) * H + i];
        float w1 = WR[(k + 1) * H + i];
        float w2 = WR[(k + 2) * H + i];
        float w3 = WR[(k + 3) * H + i];
#pragma unroll
        for (int u = 0; u < 8; u++) {
            float4 m4 = *(const float4*)&s_ae[sub * 8 + u][k];
            acc[u] = fmaf(m4.x, w0, acc[u]);
            acc[u] = fmaf(m4.y, w1, acc[u]);
            acc[u] = fmaf(m4.z, w2, acc[u]);
            acc[u] = fmaf(m4.w, w3, acc[u]);
        }
    }
#pragma unroll
    for (int u = 0; u < 8; u++)
        g_act[(n0 + sub * 8 + u) * H + i] = selu_f(acc[u]);
}

// segment-sum act over graph_id
__global__ void k_graphsum(const int* __restrict__ gid) {
    int idx = blockIdx.x * blockDim.x + threadIdx.x;
    if (idx >= N_NODES * H) return;
    int n = idx >> 6, i = idx & 63;
    atomicAdd(&g_gsum[gid[n] * H + i], g_act[idx]);
}

// out[b] = relu(tanh(gsum[b]) @ Wmlp + bmlp) @ Wout + bout
__global__ void k_readout(const float* __restrict__ Wmlp, const float* __restrict__ bmlp,
                          const float* __restrict__ Wout, const float* __restrict__ bout,
                          float* __restrict__ out) {
    __shared__ float s_ge[64];
    __shared__ float s_red[64];
    int b = blockIdx.x, i = threadIdx.x;
    s_ge[i] = tanhf(g_gsum[b * H + i]);
    __syncthreads();
    float acc = bmlp[i];
#pragma unroll 8
    for (int k = 0; k < 64; k++) acc = fmaf(s_ge[k], Wmlp[k * H + i], acc);
    float p = fmaxf(acc, 0.f) * Wout[i];
    s_red[i] = p;
    __syncthreads();
#pragma unroll
    for (int s = 32; s > 0; s >>= 1) {
        if (i < s) s_red[i] += s_red[i + s];
        __syncthreads();
    }
    if (i == 0) out[b] = s_red[0] + bout[0];
}

extern "C" void kernel_launch(void* const* d_in, const int* in_sizes, int n_in,
                              void* d_out, int out_size) {
    const float* node_features = (const float*)d_in[0];
    const float* edge_features = (const float*)d_in[1];
    const int*   edge_domain   = (const int*)d_in[2];
    const int*   edge_range    = (const int*)d_in[3];
    const int*   graph_id      = (const int*)d_in[4];
    const float* Wm   = (const float*)d_in[5];
    const float* bm   = (const float*)d_in[6];
    const float* Ew   = (const float*)d_in[7];
    const float* Wu0  = (const float*)d_in[8];
    const float* bu0  = (const float*)d_in[9];
    const float* Wu1  = (const float*)d_in[10];
    const float* bu1  = (const float*)d_in[11];
    const float* Wae  = (const float*)d_in[12];
    const float* bae  = (const float*)d_in[13];
    const float* WR   = (const float*)d_in[14];
    const float* bR   = (const float*)d_in[15];
    const float* Wmlp = (const float*)d_in[16];
    const float* bmlp = (const float*)d_in[17];
    const float* Wout = (const float*)d_in[18];
    const float* bout = (const float*)d_in[19];
    float* out = (float*)d_out;

    // fused prep: pad h, edge MLP, cast Ew to bf16, zero g_msg
    k_prep<<<PREP_GRID, 256>>>(node_features, edge_features, Wm, bm, Ew);

    // message passing steps: fused on-the-fly GEMM, register A-fragments,
    // cp.async double-buffered B with register-pipelined fragments
    const float* Wus[2] = {Wu0, Wu1};
    const float* bus[2] = {bu0, bu1};
    dim3 gM(E_PAD / 128, KSEG);
    for (int t = 0; t < 2; t++) {
        k_medge<<<gM, 256>>>(edge_domain, edge_range);
        k_update<<<N_NODES / 32, 256>>>(Wus[t], bus[t]);  // also re-zeroes g_msg
    }

    // readout
    k_embed<<<N_NODES / 32, 256>>>(Wae, bae, WR, bR);     // also zeroes g_gsum
    k_graphsum<<<(N_NODES * H + 255) / 256, 256>>>(graph_id);
    k_readout<<<BGRAPH, 64>>>(Wmlp, bmlp, Wout, bout, out);
}